// round 2
// baseline (speedup 1.0000x reference)
#include <cuda_runtime.h>
#include <cuda_bf16.h>

#define NN 100000
#define EE 1600000

// ---------------- scratch (static device globals; no allocation) ------------
__device__ float g_dinv[NN];
__device__ int   g_src[EE];
__device__ int   g_dst[EE];
__device__ float g_norm[EE];
__device__ __align__(16) float g_bufA[NN * 64];
__device__ __align__(16) float g_bufB[NN * 64];
__device__ __align__(16) float g_bufC[NN * 64];
__device__ int   g_is64;

// ---------------- helpers ---------------------------------------------------
__device__ __forceinline__ void red_add_f32x4(float* p, float4 v) {
#if __CUDA_ARCH__ >= 900
    atomicAdd(reinterpret_cast<float4*>(p), v);
#else
    atomicAdd(p + 0, v.x);
    atomicAdd(p + 1, v.y);
    atomicAdd(p + 2, v.z);
    atomicAdd(p + 3, v.w);
#endif
}

// ---------------- small kernels ---------------------------------------------
__global__ void k_fill1(float* p, int n) {
    int i = blockIdx.x * blockDim.x + threadIdx.x;
    if (i < n) p[i] = 1.0f;
}

// Detect edge_index dtype: int64 (LE, small nonneg values) has odd int32 words == 0.
__global__ void k_detect(const int* __restrict__ ei32) {
    if (threadIdx.x == 0 && blockIdx.x == 0) {
        int allz = 1;
        for (int i = 1; i < 64; i += 2)
            if (ei32[i] != 0) allz = 0;
        g_is64 = allz;
    }
}

__global__ void k_decode(const void* __restrict__ ei,
                         int* __restrict__ src, int* __restrict__ dst,
                         float* __restrict__ deg, int E, int n) {
    int e = blockIdx.x * blockDim.x + threadIdx.x;
    if (e >= E) return;
    int s, d;
    if (g_is64) {
        const long long* p = (const long long*)ei;
        s = (int)p[e];
        d = (int)p[E + e];
    } else {
        const int* p = (const int*)ei;
        s = p[e];
        d = p[E + e];
    }
    // defensive clamp: never generate out-of-bounds addresses
    if ((unsigned)s >= (unsigned)n) s = 0;
    if ((unsigned)d >= (unsigned)n) d = 0;
    src[e] = s;
    dst[e] = d;
    atomicAdd(&deg[d], 1.0f);
}

__global__ void k_rsqrt(float* p, int n) {
    int i = blockIdx.x * blockDim.x + threadIdx.x;
    if (i < n) p[i] = rsqrtf(p[i]);
}

__global__ void k_norm(const int* __restrict__ src, const int* __restrict__ dst,
                       const float* __restrict__ dinv, float* __restrict__ nrm, int E) {
    int e = blockIdx.x * blockDim.x + threadIdx.x;
    if (e < E) nrm[e] = dinv[src[e]] * dinv[dst[e]];
}

// agg[i] = x[i] * dinv[node]^2   (self-loop init), float4-granular
template <int CPE>
__global__ void k_selfinit(const float* __restrict__ x, const float* __restrict__ dinv,
                           float* __restrict__ agg, int total4) {
    int i = blockIdx.x * blockDim.x + threadIdx.x;
    if (i >= total4) return;
    int node = i / CPE;
    float s = dinv[node];
    s *= s;
    float4 v = reinterpret_cast<const float4*>(x)[i];
    v.x *= s; v.y *= s; v.z *= s; v.w *= s;
    reinterpret_cast<float4*>(agg)[i] = v;
}

// agg[dst] += h[src] * norm[e], one thread per (edge, float4 chunk)
template <int CPE>
__global__ void k_scatter(const float* __restrict__ h,
                          const int* __restrict__ src, const int* __restrict__ dst,
                          const float* __restrict__ nrm,
                          float* __restrict__ agg, int total) {
    int t = blockIdx.x * blockDim.x + threadIdx.x;
    if (t >= total) return;
    int e = t / CPE;
    int c = t - e * CPE;
    float nm = __ldg(&nrm[e]);
    int s = __ldg(&src[e]);
    int d = __ldg(&dst[e]);
    float4 v = __ldg(reinterpret_cast<const float4*>(h) + (long long)s * CPE + c);
    v.x *= nm; v.y *= nm; v.z *= nm; v.w *= nm;
    red_add_f32x4(reinterpret_cast<float*>(reinterpret_cast<float4*>(agg) + (long long)d * CPE + c), v);
}

// out = relu(agg + b), float4-granular (32 floats/row -> 8 chunks)
__global__ void k_final(const float* __restrict__ agg, const float* __restrict__ b3,
                        float* __restrict__ out, int total4) {
    int i = blockIdx.x * blockDim.x + threadIdx.x;
    if (i >= total4) return;
    int c = i & 7;
    float4 b = reinterpret_cast<const float4*>(b3)[c];
    float4 v = reinterpret_cast<const float4*>(agg)[i];
    v.x = fmaxf(v.x + b.x, 0.0f);
    v.y = fmaxf(v.y + b.y, 0.0f);
    v.z = fmaxf(v.z + b.z, 0.0f);
    v.w = fmaxf(v.w + b.w, 0.0f);
    reinterpret_cast<float4*>(out)[i] = v;
}

// ---------------- GEMM: out = f(in) @ W^T, fused epilogues -------------------
// PRE:      xk = relu(in[k] + bpre[k])
// POSTRELU: out = relu(acc + bpost)
// DUAL:     out = acc (raw h), out2 = acc * dinv[node]^2 (self-loop init)
template <int FIN, int FOUT, int NPB, int TPN, bool PRE, bool POSTRELU, bool DUAL>
__global__ void k_gemm(const float* __restrict__ in, const float* __restrict__ W,
                       const float* __restrict__ bpre, const float* __restrict__ bpost,
                       const float* __restrict__ dinv,
                       float* __restrict__ out, float* __restrict__ out2, int n) {
    static_assert(NPB * TPN == 256, "block mapping");
    static_assert(TPN * 16 == FOUT, "16 outputs per thread");
    __shared__ __align__(16) float xs[NPB * (FIN + 1)];
    __shared__ __align__(16) float Wt[FIN * FOUT];

    int tid = threadIdx.x;
    int n0 = blockIdx.x * NPB;

    for (int i = tid; i < FIN * FOUT; i += 256) {
        int f = i / FIN, k = i - f * FIN;
        Wt[k * FOUT + f] = W[i];
    }
    for (int i = tid; i < NPB * FIN; i += 256) {
        int ln = i / FIN, k = i - ln * FIN;
        int node = n0 + ln;
        float v = 0.0f;
        if (node < n) {
            v = in[(long long)node * FIN + k];
            if (PRE) v = fmaxf(v + bpre[k], 0.0f);
        }
        xs[ln * (FIN + 1) + k] = v;
    }
    __syncthreads();

    int ln = tid / TPN;
    int fsub = tid - ln * TPN;
    int node = n0 + ln;

    float acc[16];
#pragma unroll
    for (int j = 0; j < 16; j++) acc[j] = 0.0f;

#pragma unroll 4
    for (int k = 0; k < FIN; k++) {
        float xk = xs[ln * (FIN + 1) + k];
#pragma unroll
        for (int cc = 0; cc < 4; cc++) {
            int fb = (cc * TPN + fsub) * 4;
            float4 w = *reinterpret_cast<const float4*>(&Wt[k * FOUT + fb]);
            acc[cc * 4 + 0] = fmaf(xk, w.x, acc[cc * 4 + 0]);
            acc[cc * 4 + 1] = fmaf(xk, w.y, acc[cc * 4 + 1]);
            acc[cc * 4 + 2] = fmaf(xk, w.z, acc[cc * 4 + 2]);
            acc[cc * 4 + 3] = fmaf(xk, w.w, acc[cc * 4 + 3]);
        }
    }

    if (node >= n) return;

    if (DUAL) {
        float s = dinv[node];
        s *= s;
#pragma unroll
        for (int cc = 0; cc < 4; cc++) {
            int fb = (cc * TPN + fsub) * 4;
            float4 v = make_float4(acc[cc * 4 + 0], acc[cc * 4 + 1],
                                   acc[cc * 4 + 2], acc[cc * 4 + 3]);
            *reinterpret_cast<float4*>(&out[(long long)node * FOUT + fb]) = v;
            float4 v2 = make_float4(v.x * s, v.y * s, v.z * s, v.w * s);
            *reinterpret_cast<float4*>(&out2[(long long)node * FOUT + fb]) = v2;
        }
    } else {
#pragma unroll
        for (int cc = 0; cc < 4; cc++) {
            int fb = (cc * TPN + fsub) * 4;
            float4 v = make_float4(acc[cc * 4 + 0], acc[cc * 4 + 1],
                                   acc[cc * 4 + 2], acc[cc * 4 + 3]);
            if (POSTRELU) {
                float4 b = *reinterpret_cast<const float4*>(&bpost[fb]);
                v.x = fmaxf(v.x + b.x, 0.0f);
                v.y = fmaxf(v.y + b.y, 0.0f);
                v.z = fmaxf(v.z + b.z, 0.0f);
                v.w = fmaxf(v.w + b.w, 0.0f);
            }
            *reinterpret_cast<float4*>(&out[(long long)node * FOUT + fb]) = v;
        }
    }
}

// ---------------- launch -----------------------------------------------------
static inline int cdiv(long long a, int b) { return (int)((a + b - 1) / b); }

extern "C" void kernel_launch(void* const* d_in, const int* in_sizes, int n_in,
                              void* d_out, int out_size) {
    const float* x  = (const float*)d_in[0];   // [1, N, 32]
    const void*  ei = d_in[1];                 // [2, E], int32 or int64 (auto-detected)
    const float* W1 = (const float*)d_in[2];   // [64,32]
    const float* b1 = (const float*)d_in[3];
    const float* W2 = (const float*)d_in[4];   // [64,64]
    const float* b2 = (const float*)d_in[5];
    const float* W3 = (const float*)d_in[6];   // [32,64]
    const float* b3 = (const float*)d_in[7];
    float* out = (float*)d_out;

    int n = in_sizes[0] / 32;
    int E = in_sizes[1] / 2;
    if (n > NN) n = NN;
    if (E > EE) E = EE;

    float *dinv, *nrm, *bufA, *bufB, *bufC;
    int *src, *dst;
    cudaGetSymbolAddress((void**)&dinv, g_dinv);
    cudaGetSymbolAddress((void**)&src,  g_src);
    cudaGetSymbolAddress((void**)&dst,  g_dst);
    cudaGetSymbolAddress((void**)&nrm,  g_norm);
    cudaGetSymbolAddress((void**)&bufA, g_bufA);
    cudaGetSymbolAddress((void**)&bufB, g_bufB);
    cudaGetSymbolAddress((void**)&bufC, g_bufC);

    const int T = 256;

    // --- degree / normalization precompute ---
    k_detect<<<1, 32>>>((const int*)ei);
    k_fill1<<<cdiv(n, T), T>>>(dinv, n);                        // deg = 1 (self loop)
    k_decode<<<cdiv(E, T), T>>>(ei, src, dst, dinv, E, n);      // deg += 1 per dst
    k_rsqrt<<<cdiv(n, T), T>>>(dinv, n);                        // dinv = rsqrt(deg)
    k_norm<<<cdiv(E, T), T>>>(src, dst, dinv, nrm, E);          // edge norms

    // --- layer 1 (aggregate-first: agg1 = A_norm @ x, 32 dims) ---
    k_selfinit<8><<<cdiv((long long)n * 8, T), T>>>(x, dinv, bufA, n * 8);
    k_scatter<8><<<cdiv((long long)E * 8, T), T>>>(x, src, dst, nrm, bufA, E * 8);
    // out1 = relu(agg1 @ W1^T + b1) -> bufB [N,64]
    k_gemm<32, 64, 64, 4, false, true, false><<<cdiv(n, 64), T>>>(
        bufA, W1, nullptr, b1, dinv, bufB, nullptr, n);

    // --- layer 2 (matmul-first) ---
    // h2 = out1 @ W2^T -> bufC ; agg2 = h2 * dinv^2 -> bufA
    k_gemm<64, 64, 64, 4, false, false, true><<<cdiv(n, 64), T>>>(
        bufB, W2, nullptr, nullptr, dinv, bufC, bufA, n);
    k_scatter<16><<<cdiv((long long)E * 16, T), T>>>(bufC, src, dst, nrm, bufA, E * 16);

    // --- layer 3 (fused: h3 = relu(agg2+b2) @ W3^T) ---
    // h3 -> bufB [N,32] ; agg3 = h3 * dinv^2 -> bufC [N,32]
    k_gemm<64, 32, 128, 2, true, false, true><<<cdiv(n, 128), T>>>(
        bufA, W3, b2, nullptr, dinv, bufB, bufC, n);
    k_scatter<8><<<cdiv((long long)E * 8, T), T>>>(bufB, src, dst, nrm, bufC, E * 8);

    // --- output: relu(agg3 + b3) ---
    k_final<<<cdiv((long long)n * 8, T), T>>>(bufC, b3, out, n * 8);
}

// round 4
// speedup vs baseline: 1.3084x; 1.3084x over previous
#include <cuda_runtime.h>
#include <cuda_bf16.h>

#define NN 100000
#define EE 1600000

// ---------------- scratch (static device globals; no allocation) ------------
__device__ float g_dinv[NN];
__device__ int   g_hist[NN];
__device__ int   g_cnt[NN];
__device__ int   g_rowptr[NN + 1];
__device__ int   g_pscan[NN];
__device__ int   g_bsum[256];
__device__ int   g_src[EE];
__device__ int   g_dst[EE];
__device__ int   g_ssrc[EE];
__device__ float g_snrm[EE];
__device__ __align__(16) float g_bufA[NN * 64];
__device__ __align__(16) float g_bufB[NN * 64];
__device__ __align__(16) float g_bufC[NN * 64];
__device__ int   g_is64;

// ---------------- precompute kernels -----------------------------------------
__global__ void k_detect(const int* __restrict__ ei32) {
    if (threadIdx.x == 0 && blockIdx.x == 0) {
        int allz = 1;
        for (int i = 1; i < 64; i += 2)
            if (ei32[i] != 0) allz = 0;
        g_is64 = allz;
    }
}

__global__ void k_zero2(int* a, int* b, int n) {
    int i = blockIdx.x * blockDim.x + threadIdx.x;
    if (i < n) { a[i] = 0; b[i] = 0; }
}

__global__ void k_decode(const void* __restrict__ ei,
                         int* __restrict__ src, int* __restrict__ dst,
                         int* __restrict__ hist, int E, int n) {
    int e = blockIdx.x * blockDim.x + threadIdx.x;
    if (e >= E) return;
    int s, d;
    if (g_is64) {
        const long long* p = (const long long*)ei;
        s = (int)p[e];
        d = (int)p[E + e];
    } else {
        const int* p = (const int*)ei;
        s = p[e];
        d = p[E + e];
    }
    if ((unsigned)s >= (unsigned)n) s = 0;
    if ((unsigned)d >= (unsigned)n) d = 0;
    src[e] = s;
    dst[e] = d;
    atomicAdd(&hist[d], 1);
}

// 1024 elems/block exclusive scan (partial) + block sums
__global__ void k_scan_block(const int* __restrict__ hist, int* __restrict__ pscan,
                             int* __restrict__ bsum, int n) {
    __shared__ int s[256];
    int b = blockIdx.x;
    int base = b * 1024;
    int tid = threadIdx.x;
    int v[4];
    int loc = 0;
#pragma unroll
    for (int k = 0; k < 4; k++) {
        int i = base + tid * 4 + k;
        v[k] = (i < n) ? hist[i] : 0;
        loc += v[k];
    }
    s[tid] = loc;
    __syncthreads();
    for (int off = 1; off < 256; off <<= 1) {
        int t = (tid >= off) ? s[tid - off] : 0;
        __syncthreads();
        s[tid] += t;
        __syncthreads();
    }
    int run = s[tid] - loc;  // exclusive prefix of this thread
    if (tid == 255) bsum[b] = s[255];
#pragma unroll
    for (int k = 0; k < 4; k++) {
        int i = base + tid * 4 + k;
        if (i < n) pscan[i] = run;
        run += v[k];
    }
}

__global__ void k_scan_top(int* __restrict__ bsum, int nb) {
    __shared__ int s[256];
    int tid = threadIdx.x;
    int v = (tid < nb) ? bsum[tid] : 0;
    s[tid] = v;
    __syncthreads();
    for (int off = 1; off < 256; off <<= 1) {
        int t = (tid >= off) ? s[tid - off] : 0;
        __syncthreads();
        s[tid] += t;
        __syncthreads();
    }
    if (tid < nb) bsum[tid] = s[tid] - v;  // exclusive
}

__global__ void k_scan_add(const int* __restrict__ pscan, const int* __restrict__ bsum,
                           const int* __restrict__ hist, int* __restrict__ rowptr,
                           float* __restrict__ dinv, int n, int E) {
    int i = blockIdx.x * blockDim.x + threadIdx.x;
    if (i < n) {
        rowptr[i] = pscan[i] + bsum[i >> 10];
        dinv[i] = rsqrtf((float)hist[i] + 1.0f);
    }
    if (i == n) rowptr[n] = E;
}

__global__ void k_place(const int* __restrict__ src, const int* __restrict__ dst,
                        const int* __restrict__ rowptr, int* __restrict__ cnt,
                        const float* __restrict__ dinv,
                        int* __restrict__ ssrc, float* __restrict__ snrm, int E) {
    int e = blockIdx.x * blockDim.x + threadIdx.x;
    if (e >= E) return;
    int s = src[e];
    int d = dst[e];
    int pos = rowptr[d] + atomicAdd(&cnt[d], 1);
    ssrc[pos] = s;
    snrm[pos] = dinv[s] * dinv[d];
}

// ---------------- aggregation: pull over CSR ---------------------------------
// outp[v] = sum_{e in in(v)} h[src_e]*norm_e + h[v]*dinv[v]^2  (+ optional relu(+bias))
template <int CPE, bool FINAL>
__global__ void k_agg(const float* __restrict__ h, const int* __restrict__ rowptr,
                      const int* __restrict__ ssrc, const float* __restrict__ snrm,
                      const float* __restrict__ dinv, const float* __restrict__ bias,
                      float* __restrict__ outp, int n) {
    int i = blockIdx.x * blockDim.x + threadIdx.x;
    if (i >= n * CPE) return;
    int v = i / CPE;
    int c = i - v * CPE;
    const float4* h4 = reinterpret_cast<const float4*>(h);

    float sv = __ldg(&dinv[v]);
    sv *= sv;
    float4 acc = __ldg(h4 + (long long)v * CPE + c);
    acc.x *= sv; acc.y *= sv; acc.z *= sv; acc.w *= sv;

    int j = __ldg(&rowptr[v]);
    int end = __ldg(&rowptr[v + 1]);

    for (; j + 4 <= end; j += 4) {
        // front-batch all independent loads (indices+norms, then 4 gathers)
        int s0 = __ldg(&ssrc[j + 0]);
        int s1 = __ldg(&ssrc[j + 1]);
        int s2 = __ldg(&ssrc[j + 2]);
        int s3 = __ldg(&ssrc[j + 3]);
        float n0 = __ldg(&snrm[j + 0]);
        float n1 = __ldg(&snrm[j + 1]);
        float n2 = __ldg(&snrm[j + 2]);
        float n3 = __ldg(&snrm[j + 3]);
        float4 v0 = __ldg(h4 + (long long)s0 * CPE + c);
        float4 v1 = __ldg(h4 + (long long)s1 * CPE + c);
        float4 v2 = __ldg(h4 + (long long)s2 * CPE + c);
        float4 v3 = __ldg(h4 + (long long)s3 * CPE + c);
        acc.x = fmaf(v0.x, n0, acc.x); acc.y = fmaf(v0.y, n0, acc.y);
        acc.z = fmaf(v0.z, n0, acc.z); acc.w = fmaf(v0.w, n0, acc.w);
        acc.x = fmaf(v1.x, n1, acc.x); acc.y = fmaf(v1.y, n1, acc.y);
        acc.z = fmaf(v1.z, n1, acc.z); acc.w = fmaf(v1.w, n1, acc.w);
        acc.x = fmaf(v2.x, n2, acc.x); acc.y = fmaf(v2.y, n2, acc.y);
        acc.z = fmaf(v2.z, n2, acc.z); acc.w = fmaf(v2.w, n2, acc.w);
        acc.x = fmaf(v3.x, n3, acc.x); acc.y = fmaf(v3.y, n3, acc.y);
        acc.z = fmaf(v3.z, n3, acc.z); acc.w = fmaf(v3.w, n3, acc.w);
    }
    for (; j < end; j++) {
        int s = __ldg(&ssrc[j]);
        float nm = __ldg(&snrm[j]);
        float4 vv = __ldg(h4 + (long long)s * CPE + c);
        acc.x = fmaf(vv.x, nm, acc.x); acc.y = fmaf(vv.y, nm, acc.y);
        acc.z = fmaf(vv.z, nm, acc.z); acc.w = fmaf(vv.w, nm, acc.w);
    }

    if (FINAL) {
        float4 b = reinterpret_cast<const float4*>(bias)[c];
        acc.x = fmaxf(acc.x + b.x, 0.0f);
        acc.y = fmaxf(acc.y + b.y, 0.0f);
        acc.z = fmaxf(acc.z + b.z, 0.0f);
        acc.w = fmaxf(acc.w + b.w, 0.0f);
    }
    reinterpret_cast<float4*>(outp)[(long long)v * CPE + c] = acc;
}

// ---------------- GEMM: out = f(in) @ W^T, fused epilogues -------------------
// PRE:      xk = relu(in[k] + bpre[k]);  POSTRELU: out = relu(acc + bpost)
template <int FIN, int FOUT, int NPB, int TPN, bool PRE, bool POSTRELU>
__global__ void k_gemm(const float* __restrict__ in, const float* __restrict__ W,
                       const float* __restrict__ bpre, const float* __restrict__ bpost,
                       float* __restrict__ out, int n) {
    static_assert(NPB * TPN == 256, "block mapping");
    static_assert(TPN * 16 == FOUT, "16 outputs per thread");
    __shared__ __align__(16) float xs[NPB * (FIN + 1)];
    __shared__ __align__(16) float Wt[FIN * FOUT];

    int tid = threadIdx.x;
    int n0 = blockIdx.x * NPB;

    for (int i = tid; i < FIN * FOUT; i += 256) {
        int f = i / FIN, k = i - f * FIN;
        Wt[k * FOUT + f] = W[i];
    }
    for (int i = tid; i < NPB * FIN; i += 256) {
        int ln = i / FIN, k = i - ln * FIN;
        int node = n0 + ln;
        float v = 0.0f;
        if (node < n) {
            v = in[(long long)node * FIN + k];
            if (PRE) v = fmaxf(v + bpre[k], 0.0f);
        }
        xs[ln * (FIN + 1) + k] = v;
    }
    __syncthreads();

    int ln = tid / TPN;
    int fsub = tid - ln * TPN;
    int node = n0 + ln;

    float acc[16];
#pragma unroll
    for (int j = 0; j < 16; j++) acc[j] = 0.0f;

#pragma unroll 4
    for (int k = 0; k < FIN; k++) {
        float xk = xs[ln * (FIN + 1) + k];
#pragma unroll
        for (int cc = 0; cc < 4; cc++) {
            int fb = (cc * TPN + fsub) * 4;
            float4 w = *reinterpret_cast<const float4*>(&Wt[k * FOUT + fb]);
            acc[cc * 4 + 0] = fmaf(xk, w.x, acc[cc * 4 + 0]);
            acc[cc * 4 + 1] = fmaf(xk, w.y, acc[cc * 4 + 1]);
            acc[cc * 4 + 2] = fmaf(xk, w.z, acc[cc * 4 + 2]);
            acc[cc * 4 + 3] = fmaf(xk, w.w, acc[cc * 4 + 3]);
        }
    }

    if (node >= n) return;

#pragma unroll
    for (int cc = 0; cc < 4; cc++) {
        int fb = (cc * TPN + fsub) * 4;
        float4 v = make_float4(acc[cc * 4 + 0], acc[cc * 4 + 1],
                               acc[cc * 4 + 2], acc[cc * 4 + 3]);
        if (POSTRELU) {
            float4 b = *reinterpret_cast<const float4*>(&bpost[fb]);
            v.x = fmaxf(v.x + b.x, 0.0f);
            v.y = fmaxf(v.y + b.y, 0.0f);
            v.z = fmaxf(v.z + b.z, 0.0f);
            v.w = fmaxf(v.w + b.w, 0.0f);
        }
        *reinterpret_cast<float4*>(&out[(long long)node * FOUT + fb]) = v;
    }
}

// ---------------- launch -----------------------------------------------------
static inline int cdiv(long long a, int b) { return (int)((a + b - 1) / b); }

extern "C" void kernel_launch(void* const* d_in, const int* in_sizes, int n_in,
                              void* d_out, int out_size) {
    const float* x  = (const float*)d_in[0];   // [1, N, 32]
    const void*  ei = d_in[1];                 // [2, E] int32/int64 (auto-detected)
    const float* W1 = (const float*)d_in[2];   // [64,32]
    const float* b1 = (const float*)d_in[3];
    const float* W2 = (const float*)d_in[4];   // [64,64]
    const float* b2 = (const float*)d_in[5];
    const float* W3 = (const float*)d_in[6];   // [32,64]
    const float* b3 = (const float*)d_in[7];
    float* out = (float*)d_out;

    int n = in_sizes[0] / 32;
    int E = in_sizes[1] / 2;
    if (n > NN) n = NN;
    if (E > EE) E = EE;

    float *dinv, *snrm, *bufA, *bufB, *bufC;
    int *hist, *cnt, *rowptr, *pscan, *bsum, *src, *dst, *ssrc;
    cudaGetSymbolAddress((void**)&dinv,   g_dinv);
    cudaGetSymbolAddress((void**)&hist,   g_hist);
    cudaGetSymbolAddress((void**)&cnt,    g_cnt);
    cudaGetSymbolAddress((void**)&rowptr, g_rowptr);
    cudaGetSymbolAddress((void**)&pscan,  g_pscan);
    cudaGetSymbolAddress((void**)&bsum,   g_bsum);
    cudaGetSymbolAddress((void**)&src,    g_src);
    cudaGetSymbolAddress((void**)&dst,    g_dst);
    cudaGetSymbolAddress((void**)&ssrc,   g_ssrc);
    cudaGetSymbolAddress((void**)&snrm,   g_snrm);
    cudaGetSymbolAddress((void**)&bufA,   g_bufA);
    cudaGetSymbolAddress((void**)&bufB,   g_bufB);
    cudaGetSymbolAddress((void**)&bufC,   g_bufC);

    const int T = 256;
    int nb = cdiv(n, 1024);

    // --- CSR build ---
    k_detect<<<1, 32>>>((const int*)ei);
    k_zero2<<<cdiv(n, T), T>>>(hist, cnt, n);
    k_decode<<<cdiv(E, T), T>>>(ei, src, dst, hist, E, n);
    k_scan_block<<<nb, 256>>>(hist, pscan, bsum, n);
    k_scan_top<<<1, 256>>>(bsum, nb);
    k_scan_add<<<cdiv(n + 1, T), T>>>(pscan, bsum, hist, rowptr, dinv, n, E);
    k_place<<<cdiv(E, T), T>>>(src, dst, rowptr, cnt, dinv, ssrc, snrm, E);

    // --- layer 1: agg1 = A_norm @ x (32 dims), then relu(agg1 @ W1^T + b1) ---
    k_agg<8, false><<<cdiv((long long)n * 8, T), T>>>(
        x, rowptr, ssrc, snrm, dinv, nullptr, bufA, n);
    k_gemm<32, 64, 64, 4, false, true><<<cdiv(n, 64), T>>>(
        bufA, W1, nullptr, b1, bufB, n);

    // --- layer 2: h2 = out1 @ W2^T, then agg2 = A_norm @ h2 (64 dims) ---
    k_gemm<64, 64, 64, 4, false, false><<<cdiv(n, 64), T>>>(
        bufB, W2, nullptr, nullptr, bufC, n);
    k_agg<16, false><<<cdiv((long long)n * 16, T), T>>>(
        bufC, rowptr, ssrc, snrm, dinv, nullptr, bufA, n);

    // --- layer 3: h3 = relu(agg2 + b2) @ W3^T, agg3 + relu(+b3) -> out ---
    k_gemm<64, 32, 128, 2, true, false><<<cdiv(n, 128), T>>>(
        bufA, W3, b2, nullptr, bufB, n);
    k_agg<8, true><<<cdiv((long long)n * 8, T), T>>>(
        bufB, rowptr, ssrc, snrm, dinv, b3, out, n);
}

// round 5
// speedup vs baseline: 1.3854x; 1.0589x over previous
#include <cuda_runtime.h>
#include <cuda_fp16.h>

#define NN 100000
#define EE 1600000

// ---------------- scratch (static device globals; no allocation) ------------
__device__ float g_dinv[NN];
__device__ int   g_hist[NN];
__device__ int   g_cnt[NN];
__device__ int   g_rowptr[NN + 1];
__device__ int   g_pscan[NN];
__device__ int   g_bsum[256];
__device__ __align__(16) int2   g_epack[EE];      // (src, norm-as-int)
__device__ __align__(16) float  g_bufA[NN * 64];  // fp32 agg outputs
__device__ __align__(16) float  g_bufB[NN * 64];  // fp32 gemm1 output
__device__ __align__(16) __half g_hx[NN * 32];    // x fp16 / reused as h3
__device__ __align__(16) __half g_h2[NN * 64];    // h2 fp16
__device__ int   g_is64;

// ---------------- precompute kernels -----------------------------------------
__global__ void k_detect(const int* __restrict__ ei32) {
    if (threadIdx.x == 0 && blockIdx.x == 0) {
        int allz = 1;
        for (int i = 1; i < 64; i += 2)
            if (ei32[i] != 0) allz = 0;
        g_is64 = allz;
    }
}

__global__ void k_zero2(int* a, int* b, int n) {
    int i = blockIdx.x * blockDim.x + threadIdx.x;
    if (i < n) { a[i] = 0; b[i] = 0; }
}

// histogram of dst only
__global__ void k_hist(const void* __restrict__ ei, int* __restrict__ hist, int E, int n) {
    int e = blockIdx.x * blockDim.x + threadIdx.x;
    if (e >= E) return;
    int d;
    if (g_is64) d = (int)((const long long*)ei)[E + e];
    else        d = ((const int*)ei)[E + e];
    if ((unsigned)d >= (unsigned)n) d = 0;
    atomicAdd(&hist[d], 1);
}

// 1024 elems/block exclusive scan (partial) + block sums
__global__ void k_scan_block(const int* __restrict__ hist, int* __restrict__ pscan,
                             int* __restrict__ bsum, int n) {
    __shared__ int s[256];
    int b = blockIdx.x;
    int base = b * 1024;
    int tid = threadIdx.x;
    int v[4];
    int loc = 0;
#pragma unroll
    for (int k = 0; k < 4; k++) {
        int i = base + tid * 4 + k;
        v[k] = (i < n) ? hist[i] : 0;
        loc += v[k];
    }
    s[tid] = loc;
    __syncthreads();
    for (int off = 1; off < 256; off <<= 1) {
        int t = (tid >= off) ? s[tid - off] : 0;
        __syncthreads();
        s[tid] += t;
        __syncthreads();
    }
    int run = s[tid] - loc;
    if (tid == 255) bsum[b] = s[255];
#pragma unroll
    for (int k = 0; k < 4; k++) {
        int i = base + tid * 4 + k;
        if (i < n) pscan[i] = run;
        run += v[k];
    }
}

__global__ void k_scan_top(int* __restrict__ bsum, int nb) {
    __shared__ int s[256];
    int tid = threadIdx.x;
    int v = (tid < nb) ? bsum[tid] : 0;
    s[tid] = v;
    __syncthreads();
    for (int off = 1; off < 256; off <<= 1) {
        int t = (tid >= off) ? s[tid - off] : 0;
        __syncthreads();
        s[tid] += t;
        __syncthreads();
    }
    if (tid < nb) bsum[tid] = s[tid] - v;
}

__global__ void k_scan_add(const int* __restrict__ pscan, const int* __restrict__ bsum,
                           const int* __restrict__ hist, int* __restrict__ rowptr,
                           float* __restrict__ dinv, int n, int E) {
    int i = blockIdx.x * blockDim.x + threadIdx.x;
    if (i < n) {
        rowptr[i] = pscan[i] + bsum[i >> 10];
        dinv[i] = rsqrtf((float)hist[i] + 1.0f);
    }
    if (i == n) rowptr[n] = E;
}

// re-decode edges, place (src, norm) sorted by dst
__global__ void k_place(const void* __restrict__ ei, const int* __restrict__ rowptr,
                        int* __restrict__ cnt, const float* __restrict__ dinv,
                        int2* __restrict__ epack, int E, int n) {
    int e = blockIdx.x * blockDim.x + threadIdx.x;
    if (e >= E) return;
    int s, d;
    if (g_is64) {
        const long long* p = (const long long*)ei;
        s = (int)p[e];
        d = (int)p[E + e];
    } else {
        const int* p = (const int*)ei;
        s = p[e];
        d = p[E + e];
    }
    if ((unsigned)s >= (unsigned)n) s = 0;
    if ((unsigned)d >= (unsigned)n) d = 0;
    int pos = rowptr[d] + atomicAdd(&cnt[d], 1);
    epack[pos] = make_int2(s, __float_as_int(dinv[s] * dinv[d]));
}

// fp32 -> fp16 conversion (8 values per thread)
__global__ void k_tohalf(const float* __restrict__ in, __half* __restrict__ outh, int total8) {
    int i = blockIdx.x * blockDim.x + threadIdx.x;
    if (i >= total8) return;
    float4 a = reinterpret_cast<const float4*>(in)[i * 2 + 0];
    float4 b = reinterpret_cast<const float4*>(in)[i * 2 + 1];
    __half2 h0 = __floats2half2_rn(a.x, a.y);
    __half2 h1 = __floats2half2_rn(a.z, a.w);
    __half2 h2 = __floats2half2_rn(b.x, b.y);
    __half2 h3 = __floats2half2_rn(b.z, b.w);
    uint4 u;
    u.x = *reinterpret_cast<unsigned*>(&h0);
    u.y = *reinterpret_cast<unsigned*>(&h1);
    u.z = *reinterpret_cast<unsigned*>(&h2);
    u.w = *reinterpret_cast<unsigned*>(&h3);
    reinterpret_cast<uint4*>(outh)[i] = u;
}

// ---------------- aggregation: pull over CSR, fp16 features ------------------
// Each thread: node v, chunk c of 8 dims (16B of halves). Accumulate fp32.
// outp[v] = sum_e h[src_e]*norm_e + h[v]*dinv[v]^2  (+ optional relu(+bias))
template <int CPE, bool FINAL>
__global__ void k_agg_h(const __half* __restrict__ h, const int* __restrict__ rowptr,
                        const int2* __restrict__ epack, const float* __restrict__ dinv,
                        const float* __restrict__ bias, float* __restrict__ outp, int n) {
    int i = blockIdx.x * blockDim.x + threadIdx.x;
    if (i >= n * CPE) return;
    int v = i / CPE;
    int c = i - v * CPE;
    const float4* h4 = reinterpret_cast<const float4*>(h);  // 16B = 8 halves

    float acc[8];
    {
        float sv = __ldg(&dinv[v]);
        sv *= sv;
        float4 p = __ldg(h4 + (long long)v * CPE + c);
        const __half2* hp = reinterpret_cast<const __half2*>(&p);
#pragma unroll
        for (int k = 0; k < 4; k++) {
            float2 t = __half22float2(hp[k]);
            acc[2 * k + 0] = t.x * sv;
            acc[2 * k + 1] = t.y * sv;
        }
    }

    int j = __ldg(&rowptr[v]);
    int end = __ldg(&rowptr[v + 1]);

    for (; j + 4 <= end; j += 4) {
        int2 e0 = __ldg(&epack[j + 0]);
        int2 e1 = __ldg(&epack[j + 1]);
        int2 e2 = __ldg(&epack[j + 2]);
        int2 e3 = __ldg(&epack[j + 3]);
        float4 g0 = __ldg(h4 + (long long)e0.x * CPE + c);
        float4 g1 = __ldg(h4 + (long long)e1.x * CPE + c);
        float4 g2 = __ldg(h4 + (long long)e2.x * CPE + c);
        float4 g3 = __ldg(h4 + (long long)e3.x * CPE + c);
        float n0 = __int_as_float(e0.y);
        float n1 = __int_as_float(e1.y);
        float n2 = __int_as_float(e2.y);
        float n3 = __int_as_float(e3.y);
        const __half2* p0 = reinterpret_cast<const __half2*>(&g0);
        const __half2* p1 = reinterpret_cast<const __half2*>(&g1);
        const __half2* p2 = reinterpret_cast<const __half2*>(&g2);
        const __half2* p3 = reinterpret_cast<const __half2*>(&g3);
#pragma unroll
        for (int k = 0; k < 4; k++) {
            float2 t0 = __half22float2(p0[k]);
            float2 t1 = __half22float2(p1[k]);
            float2 t2 = __half22float2(p2[k]);
            float2 t3 = __half22float2(p3[k]);
            acc[2 * k + 0] = fmaf(t0.x, n0, acc[2 * k + 0]);
            acc[2 * k + 1] = fmaf(t0.y, n0, acc[2 * k + 1]);
            acc[2 * k + 0] = fmaf(t1.x, n1, acc[2 * k + 0]);
            acc[2 * k + 1] = fmaf(t1.y, n1, acc[2 * k + 1]);
            acc[2 * k + 0] = fmaf(t2.x, n2, acc[2 * k + 0]);
            acc[2 * k + 1] = fmaf(t2.y, n2, acc[2 * k + 1]);
            acc[2 * k + 0] = fmaf(t3.x, n3, acc[2 * k + 0]);
            acc[2 * k + 1] = fmaf(t3.y, n3, acc[2 * k + 1]);
        }
    }
    for (; j < end; j++) {
        int2 e = __ldg(&epack[j]);
        float nm = __int_as_float(e.y);
        float4 g = __ldg(h4 + (long long)e.x * CPE + c);
        const __half2* p = reinterpret_cast<const __half2*>(&g);
#pragma unroll
        for (int k = 0; k < 4; k++) {
            float2 t = __half22float2(p[k]);
            acc[2 * k + 0] = fmaf(t.x, nm, acc[2 * k + 0]);
            acc[2 * k + 1] = fmaf(t.y, nm, acc[2 * k + 1]);
        }
    }

    float4 o0 = make_float4(acc[0], acc[1], acc[2], acc[3]);
    float4 o1 = make_float4(acc[4], acc[5], acc[6], acc[7]);
    if (FINAL) {
        float4 b0 = reinterpret_cast<const float4*>(bias)[c * 2 + 0];
        float4 b1 = reinterpret_cast<const float4*>(bias)[c * 2 + 1];
        o0.x = fmaxf(o0.x + b0.x, 0.0f); o0.y = fmaxf(o0.y + b0.y, 0.0f);
        o0.z = fmaxf(o0.z + b0.z, 0.0f); o0.w = fmaxf(o0.w + b0.w, 0.0f);
        o1.x = fmaxf(o1.x + b1.x, 0.0f); o1.y = fmaxf(o1.y + b1.y, 0.0f);
        o1.z = fmaxf(o1.z + b1.z, 0.0f); o1.w = fmaxf(o1.w + b1.w, 0.0f);
    }
    float4* op = reinterpret_cast<float4*>(outp) + (long long)i * 2;
    op[0] = o0;
    op[1] = o1;
}

// ---------------- GEMM: out = f(in) @ W^T, fused epilogues -------------------
// PRE: xk = relu(in[k]+bpre[k]);  POSTRELU: out = relu(acc+bpost);  STOREH: fp16 out
template <int FIN, int FOUT, int NPB, int TPN, bool PRE, bool POSTRELU, bool STOREH>
__global__ void k_gemm(const float* __restrict__ in, const float* __restrict__ W,
                       const float* __restrict__ bpre, const float* __restrict__ bpost,
                       float* __restrict__ out, __half* __restrict__ outh, int n) {
    static_assert(NPB * TPN == 256, "block mapping");
    static_assert(TPN * 16 == FOUT, "16 outputs per thread");
    __shared__ __align__(16) float xs[NPB * (FIN + 1)];
    __shared__ __align__(16) float Wt[FIN * FOUT];

    int tid = threadIdx.x;
    int n0 = blockIdx.x * NPB;

    for (int i = tid; i < FIN * FOUT; i += 256) {
        int f = i / FIN, k = i - f * FIN;
        Wt[k * FOUT + f] = W[i];
    }
    for (int i = tid; i < NPB * FIN; i += 256) {
        int ln = i / FIN, k = i - ln * FIN;
        int node = n0 + ln;
        float v = 0.0f;
        if (node < n) {
            v = in[(long long)node * FIN + k];
            if (PRE) v = fmaxf(v + bpre[k], 0.0f);
        }
        xs[ln * (FIN + 1) + k] = v;
    }
    __syncthreads();

    int ln = tid / TPN;
    int fsub = tid - ln * TPN;
    int node = n0 + ln;

    float acc[16];
#pragma unroll
    for (int j = 0; j < 16; j++) acc[j] = 0.0f;

#pragma unroll 4
    for (int k = 0; k < FIN; k++) {
        float xk = xs[ln * (FIN + 1) + k];
#pragma unroll
        for (int cc = 0; cc < 4; cc++) {
            int fb = (cc * TPN + fsub) * 4;
            float4 w = *reinterpret_cast<const float4*>(&Wt[k * FOUT + fb]);
            acc[cc * 4 + 0] = fmaf(xk, w.x, acc[cc * 4 + 0]);
            acc[cc * 4 + 1] = fmaf(xk, w.y, acc[cc * 4 + 1]);
            acc[cc * 4 + 2] = fmaf(xk, w.z, acc[cc * 4 + 2]);
            acc[cc * 4 + 3] = fmaf(xk, w.w, acc[cc * 4 + 3]);
        }
    }

    if (node >= n) return;

#pragma unroll
    for (int cc = 0; cc < 4; cc++) {
        int fb = (cc * TPN + fsub) * 4;
        float4 v = make_float4(acc[cc * 4 + 0], acc[cc * 4 + 1],
                               acc[cc * 4 + 2], acc[cc * 4 + 3]);
        if (POSTRELU) {
            float4 b = *reinterpret_cast<const float4*>(&bpost[fb]);
            v.x = fmaxf(v.x + b.x, 0.0f);
            v.y = fmaxf(v.y + b.y, 0.0f);
            v.z = fmaxf(v.z + b.z, 0.0f);
            v.w = fmaxf(v.w + b.w, 0.0f);
        }
        if (STOREH) {
            __half2 h0 = __floats2half2_rn(v.x, v.y);
            __half2 h1 = __floats2half2_rn(v.z, v.w);
            uint2 u;
            u.x = *reinterpret_cast<unsigned*>(&h0);
            u.y = *reinterpret_cast<unsigned*>(&h1);
            *reinterpret_cast<uint2*>(&outh[(long long)node * FOUT + fb]) = u;
        } else {
            *reinterpret_cast<float4*>(&out[(long long)node * FOUT + fb]) = v;
        }
    }
}

// ---------------- launch -----------------------------------------------------
static inline int cdiv(long long a, int b) { return (int)((a + b - 1) / b); }

extern "C" void kernel_launch(void* const* d_in, const int* in_sizes, int n_in,
                              void* d_out, int out_size) {
    const float* x  = (const float*)d_in[0];   // [1, N, 32]
    const void*  ei = d_in[1];                 // [2, E] int32/int64 auto-detected
    const float* W1 = (const float*)d_in[2];   // [64,32]
    const float* b1 = (const float*)d_in[3];
    const float* W2 = (const float*)d_in[4];   // [64,64]
    const float* b2 = (const float*)d_in[5];
    const float* W3 = (const float*)d_in[6];   // [32,64]
    const float* b3 = (const float*)d_in[7];
    float* out = (float*)d_out;

    int n = in_sizes[0] / 32;
    int E = in_sizes[1] / 2;
    if (n > NN) n = NN;
    if (E > EE) E = EE;

    float *dinv, *bufA, *bufB;
    int *hist, *cnt, *rowptr, *pscan, *bsum;
    int2 *epack;
    __half *hx, *h2;
    cudaGetSymbolAddress((void**)&dinv,   g_dinv);
    cudaGetSymbolAddress((void**)&hist,   g_hist);
    cudaGetSymbolAddress((void**)&cnt,    g_cnt);
    cudaGetSymbolAddress((void**)&rowptr, g_rowptr);
    cudaGetSymbolAddress((void**)&pscan,  g_pscan);
    cudaGetSymbolAddress((void**)&bsum,   g_bsum);
    cudaGetSymbolAddress((void**)&epack,  g_epack);
    cudaGetSymbolAddress((void**)&bufA,   g_bufA);
    cudaGetSymbolAddress((void**)&bufB,   g_bufB);
    cudaGetSymbolAddress((void**)&hx,     g_hx);
    cudaGetSymbolAddress((void**)&h2,     g_h2);

    const int T = 256;
    int nb = cdiv(n, 1024);

    // --- CSR build + x->fp16 ---
    k_detect<<<1, 32>>>((const int*)ei);
    k_zero2<<<cdiv(n, T), T>>>(hist, cnt, n);
    k_tohalf<<<cdiv((long long)n * 4, T), T>>>(x, hx, n * 4);
    k_hist<<<cdiv(E, T), T>>>(ei, hist, E, n);
    k_scan_block<<<nb, 256>>>(hist, pscan, bsum, n);
    k_scan_top<<<1, 256>>>(bsum, nb);
    k_scan_add<<<cdiv(n + 1, T), T>>>(pscan, bsum, hist, rowptr, dinv, n, E);
    k_place<<<cdiv(E, T), T>>>(ei, rowptr, cnt, dinv, epack, E, n);

    // --- layer 1: agg1 = A_norm @ x (fp16 gather, 32 dims) -> bufA fp32 ---
    k_agg_h<4, false><<<cdiv((long long)n * 4, T), T>>>(
        hx, rowptr, epack, dinv, nullptr, bufA, n);
    // out1 = relu(agg1 @ W1^T + b1) -> bufB fp32 [N,64]
    k_gemm<32, 64, 64, 4, false, true, false><<<cdiv(n, 64), T>>>(
        bufA, W1, nullptr, b1, bufB, nullptr, n);

    // --- layer 2: h2 = out1 @ W2^T (fp16 out), agg2 -> bufA fp32 [N,64] ---
    k_gemm<64, 64, 64, 4, false, false, true><<<cdiv(n, 64), T>>>(
        bufB, W2, nullptr, nullptr, nullptr, h2, n);
    k_agg_h<8, false><<<cdiv((long long)n * 8, T), T>>>(
        h2, rowptr, epack, dinv, nullptr, bufA, n);

    // --- layer 3: h3 = relu(agg2+b2) @ W3^T (fp16 out, reuse hx) ---
    k_gemm<64, 32, 128, 2, true, false, true><<<cdiv(n, 128), T>>>(
        bufA, W3, b2, nullptr, nullptr, hx, n);
    // agg3 + relu(+b3) -> out fp32
    k_agg_h<4, true><<<cdiv((long long)n * 4, T), T>>>(
        hx, rowptr, epack, dinv, b3, out, n);
}

// round 6
// speedup vs baseline: 1.4159x; 1.0220x over previous
#include <cuda_runtime.h>
#include <cuda_fp16.h>

#define NN 100000
#define EE 1600000

// ---------------- scratch (static device globals; no allocation) ------------
__device__ float g_dinv[NN];
__device__ int   g_hist[NN];
__device__ int   g_cnt[NN];
__device__ int   g_rowptr[NN + 1];
__device__ int   g_pscan[NN];
__device__ int   g_bsum[256];
__device__ __align__(16) int2   g_epack[EE];      // (src, norm-as-int)
__device__ __align__(16) float  g_bufA[NN * 64];  // fp32 agg outputs
__device__ __align__(16) float  g_bufB[NN * 64];  // fp32 gemm1 output
__device__ __align__(16) __half g_hx[NN * 32];    // x fp16 / reused as h3
__device__ __align__(16) __half g_h2[NN * 64];    // h2 fp16
__device__ int   g_is64;

// ---------------- packed f32x2 FMA helpers -----------------------------------
__device__ __forceinline__ unsigned long long pack_dup(float x) {
    unsigned long long r;
    unsigned u = __float_as_uint(x);
    asm("mov.b64 %0, {%1, %1};" : "=l"(r) : "r"(u));
    return r;
}
__device__ __forceinline__ unsigned long long fma_f32x2(
    unsigned long long a, unsigned long long b, unsigned long long c) {
    unsigned long long d;
    asm("fma.rn.f32x2 %0, %1, %2, %3;" : "=l"(d) : "l"(a), "l"(b), "l"(c));
    return d;
}
__device__ __forceinline__ float2 unpack_f32x2(unsigned long long v) {
    unsigned lo, hi;
    asm("mov.b64 {%0, %1}, %2;" : "=r"(lo), "=r"(hi) : "l"(v));
    return make_float2(__uint_as_float(lo), __uint_as_float(hi));
}

// ---------------- fused precompute: detect + zero + x->fp16 -------------------
// grid covers n*4 threads (tohalf); first n threads also zero hist/cnt.
__global__ void k_pre(const int* __restrict__ ei32, const float* __restrict__ x,
                      __half* __restrict__ hx, int* __restrict__ hist,
                      int* __restrict__ cnt, int n) {
    int i = blockIdx.x * blockDim.x + threadIdx.x;
    if (i == 0) {
        int allz = 1;
        for (int k = 1; k < 64; k += 2)
            if (ei32[k] != 0) allz = 0;
        g_is64 = allz;
    }
    if (i < n) { hist[i] = 0; cnt[i] = 0; }
    if (i < n * 4) {
        float4 a = reinterpret_cast<const float4*>(x)[i * 2 + 0];
        float4 b = reinterpret_cast<const float4*>(x)[i * 2 + 1];
        __half2 h0 = __floats2half2_rn(a.x, a.y);
        __half2 h1 = __floats2half2_rn(a.z, a.w);
        __half2 h2 = __floats2half2_rn(b.x, b.y);
        __half2 h3 = __floats2half2_rn(b.z, b.w);
        uint4 u;
        u.x = *reinterpret_cast<unsigned*>(&h0);
        u.y = *reinterpret_cast<unsigned*>(&h1);
        u.z = *reinterpret_cast<unsigned*>(&h2);
        u.w = *reinterpret_cast<unsigned*>(&h3);
        reinterpret_cast<uint4*>(hx)[i] = u;
    }
}

// histogram of dst, 4 edges per thread
__global__ void k_hist4(const void* __restrict__ ei, int* __restrict__ hist, int E, int n) {
    int i = blockIdx.x * blockDim.x + threadIdx.x;
    int base = i * 4;
    if (base >= E) return;
    int d[4];
    if (g_is64) {
        const long long* p = (const long long*)ei + E;  // dst row
#pragma unroll
        for (int k = 0; k < 4; k++) d[k] = (base + k < E) ? (int)p[base + k] : -1;
    } else {
        const int* p = (const int*)ei + E;
#pragma unroll
        for (int k = 0; k < 4; k++) d[k] = (base + k < E) ? p[base + k] : -1;
    }
#pragma unroll
    for (int k = 0; k < 4; k++) {
        if (base + k < E) {
            int dd = d[k];
            if ((unsigned)dd >= (unsigned)n) dd = 0;
            atomicAdd(&hist[dd], 1);
        }
    }
}

// 1024 elems/block exclusive scan (partial) + block sums
__global__ void k_scan_block(const int* __restrict__ hist, int* __restrict__ pscan,
                             int* __restrict__ bsum, int n) {
    __shared__ int s[256];
    int b = blockIdx.x;
    int base = b * 1024;
    int tid = threadIdx.x;
    int v[4];
    int loc = 0;
#pragma unroll
    for (int k = 0; k < 4; k++) {
        int i = base + tid * 4 + k;
        v[k] = (i < n) ? hist[i] : 0;
        loc += v[k];
    }
    s[tid] = loc;
    __syncthreads();
    for (int off = 1; off < 256; off <<= 1) {
        int t = (tid >= off) ? s[tid - off] : 0;
        __syncthreads();
        s[tid] += t;
        __syncthreads();
    }
    int run = s[tid] - loc;
    if (tid == 255) bsum[b] = s[255];
#pragma unroll
    for (int k = 0; k < 4; k++) {
        int i = base + tid * 4 + k;
        if (i < n) pscan[i] = run;
        run += v[k];
    }
}

// fused: every block re-scans bsum (<=256 entries) then writes rowptr + dinv
__global__ void k_scan_add(const int* __restrict__ pscan, const int* __restrict__ bsum,
                           const int* __restrict__ hist, int* __restrict__ rowptr,
                           float* __restrict__ dinv, int n, int E, int nb) {
    __shared__ int sb[256];
    int tid = threadIdx.x;
    int v = (tid < nb) ? bsum[tid] : 0;
    sb[tid] = v;
    __syncthreads();
    for (int off = 1; off < 256; off <<= 1) {
        int t = (tid >= off) ? sb[tid - off] : 0;
        __syncthreads();
        sb[tid] += t;
        __syncthreads();
    }
    int excl = sb[tid] - v;  // exclusive prefix for block tid
    __syncthreads();
    sb[tid] = excl;
    __syncthreads();

    int i = blockIdx.x * blockDim.x + tid;
    if (i < n) {
        rowptr[i] = pscan[i] + sb[i >> 10];
        dinv[i] = rsqrtf((float)hist[i] + 1.0f);
    }
    if (i == n) rowptr[n] = E;
}

// re-decode edges, place (src, norm) sorted by dst
__global__ void k_place(const void* __restrict__ ei, const int* __restrict__ rowptr,
                        int* __restrict__ cnt, const float* __restrict__ dinv,
                        int2* __restrict__ epack, int E, int n) {
    int e = blockIdx.x * blockDim.x + threadIdx.x;
    if (e >= E) return;
    int s, d;
    if (g_is64) {
        const long long* p = (const long long*)ei;
        s = (int)p[e];
        d = (int)p[E + e];
    } else {
        const int* p = (const int*)ei;
        s = p[e];
        d = p[E + e];
    }
    if ((unsigned)s >= (unsigned)n) s = 0;
    if ((unsigned)d >= (unsigned)n) d = 0;
    int pos = rowptr[d] + atomicAdd(&cnt[d], 1);
    epack[pos] = make_int2(s, __float_as_int(dinv[s] * dinv[d]));
}

// ---------------- aggregation: pull over CSR, fp16 features ------------------
template <int CPE, bool FINAL>
__global__ void k_agg_h(const __half* __restrict__ h, const int* __restrict__ rowptr,
                        const int2* __restrict__ epack, const float* __restrict__ dinv,
                        const float* __restrict__ bias, float* __restrict__ outp, int n) {
    int i = blockIdx.x * blockDim.x + threadIdx.x;
    if (i >= n * CPE) return;
    int v = i / CPE;
    int c = i - v * CPE;
    const float4* h4 = reinterpret_cast<const float4*>(h);  // 16B = 8 halves

    float acc[8];
    {
        float sv = __ldg(&dinv[v]);
        sv *= sv;
        float4 p = __ldg(h4 + (long long)v * CPE + c);
        const __half2* hp = reinterpret_cast<const __half2*>(&p);
#pragma unroll
        for (int k = 0; k < 4; k++) {
            float2 t = __half22float2(hp[k]);
            acc[2 * k + 0] = t.x * sv;
            acc[2 * k + 1] = t.y * sv;
        }
    }

    int j = __ldg(&rowptr[v]);
    int end = __ldg(&rowptr[v + 1]);

    for (; j + 4 <= end; j += 4) {
        int2 e0 = __ldg(&epack[j + 0]);
        int2 e1 = __ldg(&epack[j + 1]);
        int2 e2 = __ldg(&epack[j + 2]);
        int2 e3 = __ldg(&epack[j + 3]);
        float4 g0 = __ldg(h4 + (long long)e0.x * CPE + c);
        float4 g1 = __ldg(h4 + (long long)e1.x * CPE + c);
        float4 g2 = __ldg(h4 + (long long)e2.x * CPE + c);
        float4 g3 = __ldg(h4 + (long long)e3.x * CPE + c);
        float n0 = __int_as_float(e0.y);
        float n1 = __int_as_float(e1.y);
        float n2 = __int_as_float(e2.y);
        float n3 = __int_as_float(e3.y);
        const __half2* p0 = reinterpret_cast<const __half2*>(&g0);
        const __half2* p1 = reinterpret_cast<const __half2*>(&g1);
        const __half2* p2 = reinterpret_cast<const __half2*>(&g2);
        const __half2* p3 = reinterpret_cast<const __half2*>(&g3);
#pragma unroll
        for (int k = 0; k < 4; k++) {
            float2 t0 = __half22float2(p0[k]);
            float2 t1 = __half22float2(p1[k]);
            float2 t2 = __half22float2(p2[k]);
            float2 t3 = __half22float2(p3[k]);
            acc[2 * k + 0] = fmaf(t0.x, n0, acc[2 * k + 0]);
            acc[2 * k + 1] = fmaf(t0.y, n0, acc[2 * k + 1]);
            acc[2 * k + 0] = fmaf(t1.x, n1, acc[2 * k + 0]);
            acc[2 * k + 1] = fmaf(t1.y, n1, acc[2 * k + 1]);
            acc[2 * k + 0] = fmaf(t2.x, n2, acc[2 * k + 0]);
            acc[2 * k + 1] = fmaf(t2.y, n2, acc[2 * k + 1]);
            acc[2 * k + 0] = fmaf(t3.x, n3, acc[2 * k + 0]);
            acc[2 * k + 1] = fmaf(t3.y, n3, acc[2 * k + 1]);
        }
    }
    for (; j < end; j++) {
        int2 e = __ldg(&epack[j]);
        float nm = __int_as_float(e.y);
        float4 g = __ldg(h4 + (long long)e.x * CPE + c);
        const __half2* p = reinterpret_cast<const __half2*>(&g);
#pragma unroll
        for (int k = 0; k < 4; k++) {
            float2 t = __half22float2(p[k]);
            acc[2 * k + 0] = fmaf(t.x, nm, acc[2 * k + 0]);
            acc[2 * k + 1] = fmaf(t.y, nm, acc[2 * k + 1]);
        }
    }

    float4 o0 = make_float4(acc[0], acc[1], acc[2], acc[3]);
    float4 o1 = make_float4(acc[4], acc[5], acc[6], acc[7]);
    if (FINAL) {
        float4 b0 = reinterpret_cast<const float4*>(bias)[c * 2 + 0];
        float4 b1 = reinterpret_cast<const float4*>(bias)[c * 2 + 1];
        o0.x = fmaxf(o0.x + b0.x, 0.0f); o0.y = fmaxf(o0.y + b0.y, 0.0f);
        o0.z = fmaxf(o0.z + b0.z, 0.0f); o0.w = fmaxf(o0.w + b0.w, 0.0f);
        o1.x = fmaxf(o1.x + b1.x, 0.0f); o1.y = fmaxf(o1.y + b1.y, 0.0f);
        o1.z = fmaxf(o1.z + b1.z, 0.0f); o1.w = fmaxf(o1.w + b1.w, 0.0f);
    }
    float4* op = reinterpret_cast<float4*>(outp) + (long long)i * 2;
    op[0] = o0;
    op[1] = o1;
}

// ---------------- GEMM with packed f32x2 FMA ---------------------------------
// PRE: xk = relu(in[k]+bpre[k]);  POSTRELU: out = relu(acc+bpost);  STOREH: fp16 out
template <int FIN, int FOUT, int NPB, int TPN, bool PRE, bool POSTRELU, bool STOREH>
__global__ void k_gemm(const float* __restrict__ in, const float* __restrict__ W,
                       const float* __restrict__ bpre, const float* __restrict__ bpost,
                       float* __restrict__ out, __half* __restrict__ outh, int n) {
    static_assert(NPB * TPN == 256, "block mapping");
    static_assert(TPN * 16 == FOUT, "16 outputs per thread");
    __shared__ __align__(16) float xs[NPB * (FIN + 1)];
    __shared__ __align__(16) float Wt[FIN * FOUT];

    int tid = threadIdx.x;
    int n0 = blockIdx.x * NPB;

    for (int i = tid; i < FIN * FOUT; i += 256) {
        int f = i / FIN, k = i - f * FIN;
        Wt[k * FOUT + f] = W[i];
    }
    for (int i = tid; i < NPB * FIN; i += 256) {
        int ln = i / FIN, k = i - ln * FIN;
        int node = n0 + ln;
        float v = 0.0f;
        if (node < n) {
            v = in[(long long)node * FIN + k];
            if (PRE) v = fmaxf(v + bpre[k], 0.0f);
        }
        xs[ln * (FIN + 1) + k] = v;
    }
    __syncthreads();

    int ln = tid / TPN;
    int fsub = tid - ln * TPN;
    int node = n0 + ln;

    unsigned long long accp[8];  // 16 fp32 accumulators as 8 f32x2 pairs
#pragma unroll
    for (int j = 0; j < 8; j++) accp[j] = 0ull;

#pragma unroll 4
    for (int k = 0; k < FIN; k++) {
        unsigned long long xx = pack_dup(xs[ln * (FIN + 1) + k]);
#pragma unroll
        for (int cc = 0; cc < 4; cc++) {
            int fb = (cc * TPN + fsub) * 4;
            ulonglong2 w = *reinterpret_cast<const ulonglong2*>(&Wt[k * FOUT + fb]);
            accp[cc * 2 + 0] = fma_f32x2(xx, w.x, accp[cc * 2 + 0]);
            accp[cc * 2 + 1] = fma_f32x2(xx, w.y, accp[cc * 2 + 1]);
        }
    }

    if (node >= n) return;

#pragma unroll
    for (int cc = 0; cc < 4; cc++) {
        int fb = (cc * TPN + fsub) * 4;
        float2 a = unpack_f32x2(accp[cc * 2 + 0]);
        float2 b = unpack_f32x2(accp[cc * 2 + 1]);
        float4 v = make_float4(a.x, a.y, b.x, b.y);
        if (POSTRELU) {
            float4 bb = *reinterpret_cast<const float4*>(&bpost[fb]);
            v.x = fmaxf(v.x + bb.x, 0.0f);
            v.y = fmaxf(v.y + bb.y, 0.0f);
            v.z = fmaxf(v.z + bb.z, 0.0f);
            v.w = fmaxf(v.w + bb.w, 0.0f);
        }
        if (STOREH) {
            __half2 h0 = __floats2half2_rn(v.x, v.y);
            __half2 h1 = __floats2half2_rn(v.z, v.w);
            uint2 u;
            u.x = *reinterpret_cast<unsigned*>(&h0);
            u.y = *reinterpret_cast<unsigned*>(&h1);
            *reinterpret_cast<uint2*>(&outh[(long long)node * FOUT + fb]) = u;
        } else {
            *reinterpret_cast<float4*>(&out[(long long)node * FOUT + fb]) = v;
        }
    }
}

// ---------------- launch -----------------------------------------------------
static inline int cdiv(long long a, int b) { return (int)((a + b - 1) / b); }

extern "C" void kernel_launch(void* const* d_in, const int* in_sizes, int n_in,
                              void* d_out, int out_size) {
    const float* x  = (const float*)d_in[0];   // [1, N, 32]
    const void*  ei = d_in[1];                 // [2, E] int32/int64 auto-detected
    const float* W1 = (const float*)d_in[2];   // [64,32]
    const float* b1 = (const float*)d_in[3];
    const float* W2 = (const float*)d_in[4];   // [64,64]
    const float* b2 = (const float*)d_in[5];
    const float* W3 = (const float*)d_in[6];   // [32,64]
    const float* b3 = (const float*)d_in[7];
    float* out = (float*)d_out;

    int n = in_sizes[0] / 32;
    int E = in_sizes[1] / 2;
    if (n > NN) n = NN;
    if (E > EE) E = EE;

    float *dinv, *bufA, *bufB;
    int *hist, *cnt, *rowptr, *pscan, *bsum;
    int2 *epack;
    __half *hx, *h2;
    cudaGetSymbolAddress((void**)&dinv,   g_dinv);
    cudaGetSymbolAddress((void**)&hist,   g_hist);
    cudaGetSymbolAddress((void**)&cnt,    g_cnt);
    cudaGetSymbolAddress((void**)&rowptr, g_rowptr);
    cudaGetSymbolAddress((void**)&pscan,  g_pscan);
    cudaGetSymbolAddress((void**)&bsum,   g_bsum);
    cudaGetSymbolAddress((void**)&epack,  g_epack);
    cudaGetSymbolAddress((void**)&bufA,   g_bufA);
    cudaGetSymbolAddress((void**)&bufB,   g_bufB);
    cudaGetSymbolAddress((void**)&hx,     g_hx);
    cudaGetSymbolAddress((void**)&h2,     g_h2);

    const int T = 256;
    int nb = cdiv(n, 1024);

    // --- CSR build + x->fp16 (5 launches) ---
    k_pre<<<cdiv((long long)n * 4, T), T>>>((const int*)ei, x, hx, hist, cnt, n);
    k_hist4<<<cdiv(cdiv(E, 4), T), T>>>(ei, hist, E, n);
    k_scan_block<<<nb, 256>>>(hist, pscan, bsum, n);
    k_scan_add<<<cdiv(n + 1, T), T>>>(pscan, bsum, hist, rowptr, dinv, n, E, nb);
    k_place<<<cdiv(E, T), T>>>(ei, rowptr, cnt, dinv, epack, E, n);

    // --- layer 1: agg1 = A_norm @ x (fp16 gather, 32 dims) -> bufA fp32 ---
    k_agg_h<4, false><<<cdiv((long long)n * 4, T), T>>>(
        hx, rowptr, epack, dinv, nullptr, bufA, n);
    k_gemm<32, 64, 64, 4, false, true, false><<<cdiv(n, 64), T>>>(
        bufA, W1, nullptr, b1, bufB, nullptr, n);

    // --- layer 2: h2 = out1 @ W2^T (fp16 out), agg2 -> bufA fp32 [N,64] ---
    k_gemm<64, 64, 64, 4, false, false, true><<<cdiv(n, 64), T>>>(
        bufB, W2, nullptr, nullptr, nullptr, h2, n);
    k_agg_h<8, false><<<cdiv((long long)n * 8, T), T>>>(
        h2, rowptr, epack, dinv, nullptr, bufA, n);

    // --- layer 3: h3 = relu(agg2+b2) @ W3^T (fp16 out, reuse hx) ---
    k_gemm<64, 32, 128, 2, true, false, true><<<cdiv(n, 128), T>>>(
        bufA, W3, b2, nullptr, nullptr, hx, n);
    // agg3 + relu(+b3) -> out fp32
    k_agg_h<4, true><<<cdiv((long long)n * 4, T), T>>>(
        hx, rowptr, epack, dinv, b3, out, n);
}